// round 16
// baseline (speedup 1.0000x reference)
#include <cuda_runtime.h>
#include <cstdint>
#include <mma.h>
#include <math.h>

using namespace nvcuda;

// ---------------- problem constants ----------------
#define Bsz   16
#define Nseq  784
#define DIM   512
#define Hh    8
#define KDIM  64
#define VDIM  256
#define RESW  28
#define QKVO  3072      // (2*64+256)*8
#define Mrows (Bsz*Nseq) // 12544
#define EPSV  1e-5f
#define SCALEV 0.125f    // 64^-0.5

// ---- packed fp32x2 (Blackwell FFMA2 path; PTX-only) ----
#define FMA_F32X2(d,a,b,c) asm("fma.rn.f32x2 %0, %1, %2, %3;" : "=l"(d) : "l"(a), "l"(b), "l"(c))
#define MUL_F32X2M(d,a,b)  asm("mul.rn.f32x2 %0, %1, %2;" : "=l"(d) : "l"(a), "l"(b))
#define PACK_FF(d,x,y)     asm("mov.b64 %0, {%1, %2};" : "=l"(d) : "f"(x), "f"(y))
#define UNPACK_FF(x,y,d)   asm("mov.b64 {%0, %1}, %2;" : "=f"(x), "=f"(y) : "l"(d))

__device__ __forceinline__ void cpa16(unsigned int dst, const void* src) {
    asm volatile("cp.async.cg.shared.global [%0], [%1], 16;" :: "r"(dst), "l"(src));
}
#define CP_COMMIT() asm volatile("cp.async.commit_group;")
#define CP_WAIT0()  asm volatile("cp.async.wait_group 0;")

__device__ __forceinline__ unsigned int smem_u32(const void* p) {
    return (unsigned int)__cvta_generic_to_shared(p);
}
__device__ __forceinline__ float rn_tf32(float x) {
    float r;
    asm("cvt.rna.tf32.f32 %0, %1;" : "=f"(r) : "f"(x));
    return r;
}

// ---------------- scratch (device globals; no allocs allowed) ----------------
__device__ float g_Q[(size_t)Bsz*Hh*KDIM*Nseq];     // [bh][d][n]
__device__ float g_K[(size_t)Bsz*Hh*KDIM*Nseq];     // [bh][d][n]
__device__ float g_V[(size_t)Bsz*Hh*Nseq*VDIM];
__device__ float g_AO[(size_t)Bsz*Nseq*Hh*VDIM];    // tf32-rounded at store
__device__ float g_XR[(size_t)Mrows*DIM];           // tf32-rounded x
__device__ float g_WQ[(size_t)QKVO*DIM];            // tf32-rounded qkv_w
__device__ float g_WP[(size_t)DIM*Hh*VDIM];         // tf32-rounded proj_w

// =====================================================================
// Prepass: RN-round x / qkv_w / proj_w to tf32 (makes truncation exact)
// =====================================================================
__global__ __launch_bounds__(256) void round_tf32_kernel(
    const float* __restrict__ x, const float* __restrict__ wq,
    const float* __restrict__ wp)
{
    const size_t NX = (size_t)Mrows * DIM;
    const size_t NQ = (size_t)QKVO * DIM;
    const size_t NP = (size_t)DIM * Hh * VDIM;
    size_t i = (size_t)blockIdx.x * 1024 + threadIdx.x * 4;
    size_t stride = (size_t)gridDim.x * 1024;
    for (size_t s = i; s < NX; s += stride) {
        float4 v = *(const float4*)(x + s);
        v.x = rn_tf32(v.x); v.y = rn_tf32(v.y);
        v.z = rn_tf32(v.z); v.w = rn_tf32(v.w);
        *(float4*)(g_XR + s) = v;
    }
    for (size_t s = i; s < NQ; s += stride) {
        float4 v = *(const float4*)(wq + s);
        v.x = rn_tf32(v.x); v.y = rn_tf32(v.y);
        v.z = rn_tf32(v.z); v.w = rn_tf32(v.w);
        *(float4*)(g_WQ + s) = v;
    }
    for (size_t s = i; s < NP; s += stride) {
        float4 v = *(const float4*)(wp + s);
        v.x = rn_tf32(v.x); v.y = rn_tf32(v.y);
        v.z = rn_tf32(v.z); v.w = rn_tf32(v.w);
        *(float4*)(g_WP + s) = v;
    }
}

// =====================================================================
// GEMM 1 (TF32 WMMA, cp.async double-buffered, 2 CTAs/SM):
// qkv = BN(xr @ wq^T). smem = 83968 B dynamic.  (round 13 verified)
// =====================================================================
#define GEMM_SMEM 83968

__global__ __launch_bounds__(256, 2) void gemm_qkv_kernel(
    const float* __restrict__ gamma, const float* __restrict__ beta,
    const float* __restrict__ mean, const float* __restrict__ var)
{
    extern __shared__ float gsm[];
    float (*As)[128][36] = (float(*)[128][36])gsm;            // [2][128][36]
    float (*Bs)[128][36] = (float(*)[128][36])(gsm + 9216);   // [2][128][36]
    float (*stage)[320]  = (float(*)[320])(gsm + 18432);      // [8][320]

    const float* A = g_XR;
    const float* W = g_WQ;
    const int K  = DIM;
    const int bm = blockIdx.x * 128;
    const int bn = blockIdx.y * 128;
    const int tid  = threadIdx.x;
    const int wid  = tid >> 5;
    const int lane = tid & 31;
    const int wm = wid & 3;
    const int wn = wid >> 2;

    wmma::fragment<wmma::accumulator, 16, 16, 8, float> cf[2][4];
#pragma unroll
    for (int mi = 0; mi < 2; mi++)
#pragma unroll
        for (int ni = 0; ni < 4; ni++)
            wmma::fill_fragment(cf[mi][ni], 0.f);

#pragma unroll
    for (int i = 0; i < 4; i++) {
        int g = tid + i * 256;
        int row = g >> 3, c4 = (g & 7) << 2;
        cpa16(smem_u32(&As[0][row][c4]), A + (size_t)(bm + row) * K + c4);
        cpa16(smem_u32(&Bs[0][row][c4]), W + (size_t)(bn + row) * K + c4);
    }
    CP_COMMIT();

    for (int k0 = 0; k0 < K; k0 += 32) {
        const int buf = (k0 >> 5) & 1;
        CP_WAIT0();
        __syncthreads();

        if (k0 + 32 < K) {
#pragma unroll
            for (int i = 0; i < 4; i++) {
                int g = tid + i * 256;
                int row = g >> 3, c4 = (g & 7) << 2;
                cpa16(smem_u32(&As[buf ^ 1][row][c4]),
                      A + (size_t)(bm + row) * K + k0 + 32 + c4);
                cpa16(smem_u32(&Bs[buf ^ 1][row][c4]),
                      W + (size_t)(bn + row) * K + k0 + 32 + c4);
            }
        }
        CP_COMMIT();

#pragma unroll
        for (int kk = 0; kk < 32; kk += 8) {
            wmma::fragment<wmma::matrix_b, 16, 16, 8, wmma::precision::tf32, wmma::col_major> bf[4];
#pragma unroll
            for (int ni = 0; ni < 4; ni++)
                wmma::load_matrix_sync(bf[ni], &Bs[buf][wn * 64 + ni * 16][kk], 36);
#pragma unroll
            for (int mi = 0; mi < 2; mi++) {
                wmma::fragment<wmma::matrix_a, 16, 16, 8, wmma::precision::tf32, wmma::row_major> af;
                wmma::load_matrix_sync(af, &As[buf][wm * 32 + mi * 16][kk], 36);
#pragma unroll
                for (int ni = 0; ni < 4; ni++)
                    wmma::mma_sync(cf[mi][ni], af, bf[ni], cf[mi][ni]);
            }
        }
    }

    float* st = &stage[wid][0];
    const int r0 = lane >> 3;
    const int c0 = (lane & 7) << 1;
#pragma unroll
    for (int mi = 0; mi < 2; mi++)
#pragma unroll
        for (int ni = 0; ni < 4; ni++) {
            wmma::store_matrix_sync(st, cf[mi][ni], 20, wmma::mem_row_major);
            __syncwarp();
#pragma unroll
            for (int rr = 0; rr < 4; rr++) {
                int r = r0 + rr * 4;
                int row = bm + wm * 32 + mi * 16 + r;
                int b = row / Nseq;
                int n = row - b * Nseq;
#pragma unroll
                for (int cc = 0; cc < 2; cc++) {
                    int c = c0 + cc;
                    int col = bn + wn * 64 + ni * 16 + c;
                    float sc = gamma[col] * rsqrtf(var[col] + EPSV);
                    float sh = beta[col] - mean[col] * sc;
                    float val = st[r * 20 + c] * sc + sh;
                    int h  = col / 384;
                    int rrv = col - h * 384;
                    int bh = b * Hh + h;
                    if (rrv < KDIM)
                        g_Q[((size_t)bh * KDIM + rrv) * Nseq + n] = val;
                    else if (rrv < 2 * KDIM)
                        g_K[((size_t)bh * KDIM + (rrv - KDIM)) * Nseq + n] = val;
                    else
                        g_V[((size_t)bh * Nseq + n) * VDIM + (rrv - 2 * KDIM)] = val;
                }
            }
            __syncwarp();
        }
}

// =====================================================================
// Attention v11: cp.async pipelined, no online max, S-stage packed over
// ROW pairs (q pair loaded directly as 64-bit operand; only 2 key PACKs
// per d). den reduced once post-loop.
// =====================================================================
#define NKT 25
#define ATT_SMEM 113984

__global__ __launch_bounds__(256, 2) void attn_kernel(const float* __restrict__ biases)
{
    extern __shared__ float smem[];
    float (*Qst)[68]      = (float(*)[68])smem;                     // [64 d][64 r+pad]
    float (*Kst)[64][36]  = (float(*)[64][36])(smem + 4352);        // [2][64 d][32 k+pad]
    float (*Pt)[68]       = (float(*)[68])(smem + 8960);            // [32 k][64 r+pad]
    float (*Vs)[32][256]  = (float(*)[32][256])(smem + 11136);      // [2][32 k][256]
    float* brow = smem + 27520;                                     // 784
    float* den  = smem + 28304;                                     // 64

    const int bh = blockIdx.y;
    const int b  = bh >> 3;
    const int h  = bh & 7;
    const int n0 = blockIdx.x * 64;
    const int tid  = threadIdx.x;
    const int lane = tid & 31;
    const int w    = tid >> 5;

    const float* Qb = g_Q + (size_t)bh * KDIM * Nseq;
    const float* Kb = g_K + (size_t)bh * KDIM * Nseq;
    const float* Vb = g_V + (size_t)bh * Nseq * VDIM;

    {
#pragma unroll
        for (int i = 0; i < 2; i++) {
            int g = tid + i * 256;
            int d = g >> 3, c = (g & 7) << 2;
            cpa16(smem_u32(&Kst[0][d][c]), Kb + (size_t)d * Nseq + c);
        }
#pragma unroll
        for (int i = 0; i < 8; i++) {
            int g = tid + i * 256;
            int mm = g >> 6, c = (g & 63) << 2;
            cpa16(smem_u32(&Vs[0][mm][c]), Vb + (size_t)mm * VDIM + c);
        }
        CP_COMMIT();
    }

    for (int i = tid; i < Nseq; i += 256) brow[i] = biases[h * Nseq + i];

#pragma unroll
    for (int i = 0; i < 4; i++) {
        int s = tid + i * 256;
        int d = s >> 4;
        int q4 = (s & 15) << 2;
        float4 v = (n0 + q4 < Nseq)
                 ? *(const float4*)(Qb + (size_t)d * Nseq + n0 + q4)
                 : make_float4(0.f, 0.f, 0.f, 0.f);
        *(float4*)&Qst[d][q4] = v;
    }

    const int sr = (tid >> 4) << 2;     // S rows (4)
    const int sc = (tid & 15) << 1;     // S keys (2)
    const int ro = w << 3;              // PV rows (8)
    const int co = lane << 2;           // PV cols (4 + 4 at +128)

    int ry[4], rx[4];
#pragma unroll
    for (int i = 0; i < 4; i++) {
        int n = n0 + sr + i;
        int nc = (n < Nseq) ? n : (Nseq - 1);
        ry[i] = nc / RESW;
        rx[i] = nc - ry[i] * RESW;
    }

    unsigned long long o2[4][8];
#pragma unroll
    for (int k = 0; k < 4; k++)
#pragma unroll
        for (int c = 0; c < 8; c++) o2[k][c] = 0ULL;

    float dl[4] = {0.f, 0.f, 0.f, 0.f};   // per-thread den partials

    for (int kt = 0; kt < NKT; kt++) {
        const int buf = kt & 1;
        const int mbase = kt * 32;

        CP_WAIT0();
        __syncthreads();   // tile kt visible; Pt/Kst/Vs reuse safe

        if (kt + 1 < NKT) {
            const int nb = mbase + 32;
#pragma unroll
            for (int i = 0; i < 2; i++) {
                int g = tid + i * 256;
                int d = g >> 3, c = (g & 7) << 2;
                if (nb + c < Nseq)
                    cpa16(smem_u32(&Kst[buf ^ 1][d][c]),
                          Kb + (size_t)d * Nseq + nb + c);
                else
                    *(float4*)&Kst[buf ^ 1][d][c] = make_float4(0.f, 0.f, 0.f, 0.f);
            }
#pragma unroll
            for (int i = 0; i < 8; i++) {
                int g = tid + i * 256;
                int mm = g >> 6, c = (g & 63) << 2;
                if (nb + mm < Nseq)
                    cpa16(smem_u32(&Vs[buf ^ 1][mm][c]),
                          Vb + (size_t)(nb + mm) * VDIM + c);
                else
                    *(float4*)&Vs[buf ^ 1][mm][c] = make_float4(0.f, 0.f, 0.f, 0.f);
            }
        }
        CP_COMMIT();

        // ---- S = Q.K^T: packed over ROW pairs (q pairs contiguous) ----
        // t2[rp][j]: rows {sr+2rp, sr+2rp+1}, key j
        unsigned long long t2[2][2] = {{0ULL, 0ULL}, {0ULL, 0ULL}};
#pragma unroll
        for (int d = 0; d < KDIM; d++) {
            ulonglong2 qq2 = *(const ulonglong2*)&Qst[d][sr];   // {q0,q1},{q2,q3}
            float2 kv = *(const float2*)&Kst[buf][d][sc];
            unsigned long long k0, k1;
            PACK_FF(k0, kv.x, kv.x);
            PACK_FF(k1, kv.y, kv.y);
            FMA_F32X2(t2[0][0], qq2.x, k0, t2[0][0]);
            FMA_F32X2(t2[0][1], qq2.x, k1, t2[0][1]);
            FMA_F32X2(t2[1][0], qq2.y, k0, t2[1][0]);
            FMA_F32X2(t2[1][1], qq2.y, k1, t2[1][1]);
        }
        float s4[4][2];
        UNPACK_FF(s4[0][0], s4[1][0], t2[0][0]);
        UNPACK_FF(s4[0][1], s4[1][1], t2[0][1]);
        UNPACK_FF(s4[2][0], s4[3][0], t2[1][0]);
        UNPACK_FF(s4[2][1], s4[3][1], t2[1][1]);

        int m0 = mbase + sc, m1 = m0 + 1;
        bool v0 = (m0 < Nseq), v1 = (m1 < Nseq);
        int mc0 = v0 ? m0 : (Nseq - 1);
        int mc1 = v1 ? m1 : (Nseq - 1);
        int my0 = mc0 / RESW, mx0 = mc0 - my0 * RESW;
        int my1 = mc1 / RESW, mx1 = mc1 - my1 * RESW;

        // ---- softmax numerators (no max); accumulate per-thread den ----
        float p0v[4], p1v[4];
#pragma unroll
        for (int i = 0; i < 4; i++) {
            float sv0 = v0 ? (s4[i][0] * SCALEV + brow[abs(ry[i]-my0) * RESW + abs(rx[i]-mx0)]) : -1e30f;
            float sv1 = v1 ? (s4[i][1] * SCALEV + brow[abs(ry[i]-my1) * RESW + abs(rx[i]-mx1)]) : -1e30f;
            p0v[i] = __expf(sv0);
            p1v[i] = __expf(sv1);
            dl[i] += p0v[i] + p1v[i];
        }
        *(float4*)&Pt[sc][sr]     = make_float4(p0v[0], p0v[1], p0v[2], p0v[3]);
        *(float4*)&Pt[sc + 1][sr] = make_float4(p1v[0], p1v[1], p1v[2], p1v[3]);
        __syncwarp();   // Pt rows for this warp's PV are warp-local

        // ---- PV: row-pair packed FMA2 over 32 keys ----
#pragma unroll 2
        for (int mm = 0; mm < 32; mm++) {
            ulonglong2 pA = *(const ulonglong2*)&Pt[mm][ro];
            ulonglong2 pB = *(const ulonglong2*)&Pt[mm][ro + 4];
            unsigned long long p2[4] = {pA.x, pA.y, pB.x, pB.y};
            float4 va = *(const float4*)&Vs[buf][mm][co];
            float4 vb = *(const float4*)&Vs[buf][mm][128 + co];
            unsigned long long vd[8];
            PACK_FF(vd[0], va.x, va.x); PACK_FF(vd[1], va.y, va.y);
            PACK_FF(vd[2], va.z, va.z); PACK_FF(vd[3], va.w, va.w);
            PACK_FF(vd[4], vb.x, vb.x); PACK_FF(vd[5], vb.y, vb.y);
            PACK_FF(vd[6], vb.z, vb.z); PACK_FF(vd[7], vb.w, vb.w);
#pragma unroll
            for (int k = 0; k < 4; k++)
#pragma unroll
                for (int c = 0; c < 8; c++)
                    FMA_F32X2(o2[k][c], p2[k], vd[c], o2[k][c]);
        }
    }

    // ---- final den reduction (once): 16-lane group per row block ----
#pragma unroll
    for (int i = 0; i < 4; i++) {
        float ps = dl[i];
#pragma unroll
        for (int off = 8; off; off >>= 1)
            ps += __shfl_xor_sync(0xffffffffu, ps, off);
        if ((tid & 15) == 0) den[sr + i] = ps;
    }
    __syncwarp();   // den rows for this warp's epilogue are warp-local

    // ---- epilogue: normalize, SiLU, RN-round to tf32, store ----
#pragma unroll
    for (int k = 0; k < 4; k++) {
        float lo[8], hi[8];
#pragma unroll
        for (int c = 0; c < 8; c++) UNPACK_FF(lo[c], hi[c], o2[k][c]);
        int r0i = ro + 2 * k;
#pragma unroll
        for (int half = 0; half < 2; half++) {
            int r = r0i + half;
            int n = n0 + r;
            if (n < Nseq) {
                float inv = 1.f / den[r];
                const float* src = half ? hi : lo;
                size_t base = ((size_t)b * Nseq + n) * (Hh * VDIM) + h * VDIM;
                float4 vv0, vv1;
                float t;
                t = src[0] * inv; vv0.x = rn_tf32(t / (1.f + __expf(-t)));
                t = src[1] * inv; vv0.y = rn_tf32(t / (1.f + __expf(-t)));
                t = src[2] * inv; vv0.z = rn_tf32(t / (1.f + __expf(-t)));
                t = src[3] * inv; vv0.w = rn_tf32(t / (1.f + __expf(-t)));
                t = src[4] * inv; vv1.x = rn_tf32(t / (1.f + __expf(-t)));
                t = src[5] * inv; vv1.y = rn_tf32(t / (1.f + __expf(-t)));
                t = src[6] * inv; vv1.z = rn_tf32(t / (1.f + __expf(-t)));
                t = src[7] * inv; vv1.w = rn_tf32(t / (1.f + __expf(-t)));
                *(float4*)(g_AO + base + co)       = vv0;
                *(float4*)(g_AO + base + 128 + co) = vv1;
            }
        }
    }
}

// =====================================================================
// GEMM 2 (TF32 WMMA, cp.async, 64x128 CTA tiles to fix wave quant):
// out = BN(AO @ wp^T). grid 196x4 = 784 CTAs; smem = 65536 B.
// 8 warps: wm = wid&3 (16 rows each), wn = wid>>2 (64 cols each).
// =====================================================================
#define GEMM2_SMEM 65536

__global__ __launch_bounds__(256, 2) void gemm_proj_kernel(
    const float* __restrict__ gamma, const float* __restrict__ beta,
    const float* __restrict__ mean, const float* __restrict__ var,
    float* __restrict__ out)
{
    extern __shared__ float gsm[];
    float (*As)[64][36]  = (float(*)[64][36])gsm;             // [2][64][36]  = 4608 f
    float (*Bs)[128][36] = (float(*)[128][36])(gsm + 4608);   // [2][128][36] = 9216 f
    float (*stage)[320]  = (float(*)[320])(gsm + 13824);      // [8][320]

    const int K  = Hh * VDIM;   // 2048
    const float* A = g_AO;
    const float* W = g_WP;
    const int bm = blockIdx.x * 64;
    const int bn = blockIdx.y * 128;
    const int tid  = threadIdx.x;
    const int wid  = tid >> 5;
    const int lane = tid & 31;
    const int wm = wid & 3;      // row group of 16
    const int wn = wid >> 2;     // col group of 64

    wmma::fragment<wmma::accumulator, 16, 16, 8, float> cf[4];
#pragma unroll
    for (int ni = 0; ni < 4; ni++)
        wmma::fill_fragment(cf[ni], 0.f);

    // prologue: tile 0
#pragma unroll
    for (int i = 0; i < 2; i++) {    // A: 64x32 = 512 float4
        int g = tid + i * 256;
        int row = g >> 3, c4 = (g & 7) << 2;
        cpa16(smem_u32(&As[0][row][c4]), A + (size_t)(bm + row) * K + c4);
    }
#pragma unroll
    for (int i = 0; i < 4; i++) {    // B: 128x32 = 1024 float4
        int g = tid + i * 256;
        int row = g >> 3, c4 = (g & 7) << 2;
        cpa16(smem_u32(&Bs[0][row][c4]), W + (size_t)(bn + row) * K + c4);
    }
    CP_COMMIT();

    for (int k0 = 0; k0 < K; k0 += 32) {
        const int buf = (k0 >> 5) & 1;
        CP_WAIT0();
        __syncthreads();

        if (k0 + 32 < K) {
#pragma unroll
            for (int i = 0; i < 2; i++) {
                int g = tid + i * 256;
                int row = g >> 3, c4 = (g & 7) << 2;
                cpa16(smem_u32(&As[buf ^ 1][row][c4]),
                      A + (size_t)(bm + row) * K + k0 + 32 + c4);
            }
#pragma unroll
            for (int i = 0; i < 4; i++) {
                int g = tid + i * 256;
                int row = g >> 3, c4 = (g & 7) << 2;
                cpa16(smem_u32(&Bs[buf ^ 1][row][c4]),
                      W + (size_t)(bn + row) * K + k0 + 32 + c4);
            }
        }
        CP_COMMIT();

#pragma unroll
        for (int kk = 0; kk < 32; kk += 8) {
            wmma::fragment<wmma::matrix_a, 16, 16, 8, wmma::precision::tf32, wmma::row_major> af;
            wmma::load_matrix_sync(af, &As[buf][wm * 16][kk], 36);
#pragma unroll
            for (int ni = 0; ni < 4; ni++) {
                wmma::fragment<wmma::matrix_b, 16, 16, 8, wmma::precision::tf32, wmma::col_major> bf;
                wmma::load_matrix_sync(bf, &Bs[buf][wn * 64 + ni * 16][kk], 36);
                wmma::mma_sync(cf[ni], af, bf, cf[ni]);
            }
        }
    }

    float* st = &stage[wid][0];
    const int r0 = lane >> 3;
    const int c0 = (lane & 7) << 1;
#pragma unroll
    for (int ni = 0; ni < 4; ni++) {
        wmma::store_matrix_sync(st, cf[ni], 20, wmma::mem_row_major);
        __syncwarp();
#pragma unroll
        for (int rr = 0; rr < 4; rr++) {
            int r = r0 + rr * 4;
            int row = bm + wm * 16 + r;
#pragma unroll
            for (int cc = 0; cc < 2; cc++) {
                int c = c0 + cc;
                int col = bn + wn * 64 + ni * 16 + c;
                float sc = gamma[col] * rsqrtf(var[col] + EPSV);
                float sh = beta[col] - mean[col] * sc;
                out[(size_t)row * DIM + col] = st[r * 20 + c] * sc + sh;
            }
        }
        __syncwarp();
    }
}

// =====================================================================
extern "C" void kernel_launch(void* const* d_in, const int* in_sizes, int n_in,
                              void* d_out, int out_size)
{
    const float* x          = (const float*)d_in[0];
    const float* qkv_w      = (const float*)d_in[1];
    const float* qkv_gamma  = (const float*)d_in[2];
    const float* qkv_beta   = (const float*)d_in[3];
    const float* qkv_mean   = (const float*)d_in[4];
    const float* qkv_var    = (const float*)d_in[5];
    const float* att_bias   = (const float*)d_in[6];
    const float* proj_w     = (const float*)d_in[7];
    const float* proj_gamma = (const float*)d_in[8];
    const float* proj_beta  = (const float*)d_in[9];
    const float* proj_mean  = (const float*)d_in[10];
    const float* proj_var   = (const float*)d_in[11];
    // d_in[12] = bias_idxs: computed analytically in-kernel

    cudaFuncSetAttribute(gemm_qkv_kernel,
                         cudaFuncAttributeMaxDynamicSharedMemorySize, GEMM_SMEM);
    cudaFuncSetAttribute(gemm_proj_kernel,
                         cudaFuncAttributeMaxDynamicSharedMemorySize, GEMM2_SMEM);
    cudaFuncSetAttribute(attn_kernel,
                         cudaFuncAttributeMaxDynamicSharedMemorySize, ATT_SMEM);

    round_tf32_kernel<<<592, 256>>>(x, qkv_w, proj_w);

    gemm_qkv_kernel<<<dim3(Mrows / 128, QKVO / 128), 256, GEMM_SMEM>>>(
        qkv_gamma, qkv_beta, qkv_mean, qkv_var);

    attn_kernel<<<dim3((Nseq + 63) / 64, Bsz * Hh), 256, ATT_SMEM>>>(att_bias);

    gemm_proj_kernel<<<dim3(Mrows / 64, DIM / 128), 256, GEMM2_SMEM>>>(
        proj_gamma, proj_beta, proj_mean, proj_var, (float*)d_out);
}

// round 17
// speedup vs baseline: 1.0559x; 1.0559x over previous
#include <cuda_runtime.h>
#include <cstdint>
#include <mma.h>
#include <math.h>

using namespace nvcuda;

// ---------------- problem constants ----------------
#define Bsz   16
#define Nseq  784
#define DIM   512
#define Hh    8
#define KDIM  64
#define VDIM  256
#define RESW  28
#define QKVO  3072      // (2*64+256)*8
#define Mrows (Bsz*Nseq) // 12544
#define EPSV  1e-5f
#define SCALEV 0.125f    // 64^-0.5
#define LOG2E  1.4426950408889634f

// ---- packed fp32x2 (Blackwell FFMA2 path; PTX-only) ----
#define FMA_F32X2(d,a,b,c) asm("fma.rn.f32x2 %0, %1, %2, %3;" : "=l"(d) : "l"(a), "l"(b), "l"(c))
#define MUL_F32X2M(d,a,b)  asm("mul.rn.f32x2 %0, %1, %2;" : "=l"(d) : "l"(a), "l"(b))
#define PACK_FF(d,x,y)     asm("mov.b64 %0, {%1, %2};" : "=l"(d) : "f"(x), "f"(y))
#define UNPACK_FF(x,y,d)   asm("mov.b64 {%0, %1}, %2;" : "=f"(x), "=f"(y) : "l"(d))

__device__ __forceinline__ void cpa16(unsigned int dst, const void* src) {
    asm volatile("cp.async.cg.shared.global [%0], [%1], 16;" :: "r"(dst), "l"(src));
}
#define CP_COMMIT() asm volatile("cp.async.commit_group;")
#define CP_WAIT0()  asm volatile("cp.async.wait_group 0;")

__device__ __forceinline__ unsigned int smem_u32(const void* p) {
    return (unsigned int)__cvta_generic_to_shared(p);
}
__device__ __forceinline__ float rn_tf32(float x) {
    float r;
    asm("cvt.rna.tf32.f32 %0, %1;" : "=f"(r) : "f"(x));
    return r;
}
__device__ __forceinline__ float ex2f(float x) {
    float r;
    asm("ex2.approx.f32 %0, %1;" : "=f"(r) : "f"(x));
    return r;
}

// ---------------- scratch (device globals; no allocs allowed) ----------------
__device__ float g_Q[(size_t)Bsz*Hh*KDIM*Nseq];     // [bh][d][n]
__device__ float g_K[(size_t)Bsz*Hh*KDIM*Nseq];     // [bh][d][n]
__device__ float g_V[(size_t)Bsz*Hh*Nseq*VDIM];
__device__ float g_AO[(size_t)Bsz*Nseq*Hh*VDIM];    // tf32-rounded at store
__device__ float g_XR[(size_t)Mrows*DIM];           // tf32-rounded x
__device__ float g_WQ[(size_t)QKVO*DIM];            // tf32-rounded qkv_w
__device__ float g_WP[(size_t)DIM*Hh*VDIM];         // tf32-rounded proj_w

// =====================================================================
// Prepass: RN-round x / qkv_w / proj_w to tf32 (makes truncation exact)
// =====================================================================
__global__ __launch_bounds__(256) void round_tf32_kernel(
    const float* __restrict__ x, const float* __restrict__ wq,
    const float* __restrict__ wp)
{
    const size_t NX = (size_t)Mrows * DIM;
    const size_t NQ = (size_t)QKVO * DIM;
    const size_t NP = (size_t)DIM * Hh * VDIM;
    size_t i = (size_t)blockIdx.x * 1024 + threadIdx.x * 4;
    size_t stride = (size_t)gridDim.x * 1024;
    for (size_t s = i; s < NX; s += stride) {
        float4 v = *(const float4*)(x + s);
        v.x = rn_tf32(v.x); v.y = rn_tf32(v.y);
        v.z = rn_tf32(v.z); v.w = rn_tf32(v.w);
        *(float4*)(g_XR + s) = v;
    }
    for (size_t s = i; s < NQ; s += stride) {
        float4 v = *(const float4*)(wq + s);
        v.x = rn_tf32(v.x); v.y = rn_tf32(v.y);
        v.z = rn_tf32(v.z); v.w = rn_tf32(v.w);
        *(float4*)(g_WQ + s) = v;
    }
    for (size_t s = i; s < NP; s += stride) {
        float4 v = *(const float4*)(wp + s);
        v.x = rn_tf32(v.x); v.y = rn_tf32(v.y);
        v.z = rn_tf32(v.z); v.w = rn_tf32(v.w);
        *(float4*)(g_WP + s) = v;
    }
}

// =====================================================================
// GEMM 1 (TF32 WMMA, cp.async double-buffered, 2 CTAs/SM):
// qkv = BN(xr @ wq^T). smem = 83968 B dynamic.  (round-13 verified)
// =====================================================================
#define GEMM_SMEM 83968

__global__ __launch_bounds__(256, 2) void gemm_qkv_kernel(
    const float* __restrict__ gamma, const float* __restrict__ beta,
    const float* __restrict__ mean, const float* __restrict__ var)
{
    extern __shared__ float gsm[];
    float (*As)[128][36] = (float(*)[128][36])gsm;            // [2][128][36]
    float (*Bs)[128][36] = (float(*)[128][36])(gsm + 9216);   // [2][128][36]
    float (*stage)[320]  = (float(*)[320])(gsm + 18432);      // [8][320]

    const float* A = g_XR;
    const float* W = g_WQ;
    const int K  = DIM;
    const int bm = blockIdx.x * 128;
    const int bn = blockIdx.y * 128;
    const int tid  = threadIdx.x;
    const int wid  = tid >> 5;
    const int lane = tid & 31;
    const int wm = wid & 3;
    const int wn = wid >> 2;

    wmma::fragment<wmma::accumulator, 16, 16, 8, float> cf[2][4];
#pragma unroll
    for (int mi = 0; mi < 2; mi++)
#pragma unroll
        for (int ni = 0; ni < 4; ni++)
            wmma::fill_fragment(cf[mi][ni], 0.f);

#pragma unroll
    for (int i = 0; i < 4; i++) {
        int g = tid + i * 256;
        int row = g >> 3, c4 = (g & 7) << 2;
        cpa16(smem_u32(&As[0][row][c4]), A + (size_t)(bm + row) * K + c4);
        cpa16(smem_u32(&Bs[0][row][c4]), W + (size_t)(bn + row) * K + c4);
    }
    CP_COMMIT();

    for (int k0 = 0; k0 < K; k0 += 32) {
        const int buf = (k0 >> 5) & 1;
        CP_WAIT0();
        __syncthreads();

        if (k0 + 32 < K) {
#pragma unroll
            for (int i = 0; i < 4; i++) {
                int g = tid + i * 256;
                int row = g >> 3, c4 = (g & 7) << 2;
                cpa16(smem_u32(&As[buf ^ 1][row][c4]),
                      A + (size_t)(bm + row) * K + k0 + 32 + c4);
                cpa16(smem_u32(&Bs[buf ^ 1][row][c4]),
                      W + (size_t)(bn + row) * K + k0 + 32 + c4);
            }
        }
        CP_COMMIT();

#pragma unroll
        for (int kk = 0; kk < 32; kk += 8) {
            wmma::fragment<wmma::matrix_b, 16, 16, 8, wmma::precision::tf32, wmma::col_major> bf[4];
#pragma unroll
            for (int ni = 0; ni < 4; ni++)
                wmma::load_matrix_sync(bf[ni], &Bs[buf][wn * 64 + ni * 16][kk], 36);
#pragma unroll
            for (int mi = 0; mi < 2; mi++) {
                wmma::fragment<wmma::matrix_a, 16, 16, 8, wmma::precision::tf32, wmma::row_major> af;
                wmma::load_matrix_sync(af, &As[buf][wm * 32 + mi * 16][kk], 36);
#pragma unroll
                for (int ni = 0; ni < 4; ni++)
                    wmma::mma_sync(cf[mi][ni], af, bf[ni], cf[mi][ni]);
            }
        }
    }

    float* st = &stage[wid][0];
    const int r0 = lane >> 3;
    const int c0 = (lane & 7) << 1;
#pragma unroll
    for (int mi = 0; mi < 2; mi++)
#pragma unroll
        for (int ni = 0; ni < 4; ni++) {
            wmma::store_matrix_sync(st, cf[mi][ni], 20, wmma::mem_row_major);
            __syncwarp();
#pragma unroll
            for (int rr = 0; rr < 4; rr++) {
                int r = r0 + rr * 4;
                int row = bm + wm * 32 + mi * 16 + r;
                int b = row / Nseq;
                int n = row - b * Nseq;
#pragma unroll
                for (int cc = 0; cc < 2; cc++) {
                    int c = c0 + cc;
                    int col = bn + wn * 64 + ni * 16 + c;
                    float sc = gamma[col] * rsqrtf(var[col] + EPSV);
                    float sh = beta[col] - mean[col] * sc;
                    float val = st[r * 20 + c] * sc + sh;
                    int h  = col / 384;
                    int rrv = col - h * 384;
                    int bh = b * Hh + h;
                    if (rrv < KDIM)
                        g_Q[((size_t)bh * KDIM + rrv) * Nseq + n] = val;
                    else if (rrv < 2 * KDIM)
                        g_K[((size_t)bh * KDIM + (rrv - KDIM)) * Nseq + n] = val;
                    else
                        g_V[((size_t)bh * Nseq + n) * VDIM + (rrv - 2 * KDIM)] = val;
                }
            }
            __syncwarp();
        }
}

// =====================================================================
// Attention v10.1 (round-15 verified structure): cp.async pipelined,
// no online max, S-stage key-pair FMA2, den reduced once post-loop.
// New: log2e folded into scale+bias -> raw EX2 (no FMUL in __expf path).
// =====================================================================
#define NKT 25
#define ATT_SMEM 113984

__global__ __launch_bounds__(256, 2) void attn_kernel(const float* __restrict__ biases)
{
    extern __shared__ float smem[];
    float (*Qst)[68]      = (float(*)[68])smem;                     // [64 d][64 r+pad]
    float (*Kst)[64][36]  = (float(*)[64][36])(smem + 4352);        // [2][64 d][32 k+pad]
    float (*Pt)[68]       = (float(*)[68])(smem + 8960);            // [32 k][64 r+pad]
    float (*Vs)[32][256]  = (float(*)[32][256])(smem + 11136);      // [2][32 k][256]
    float* brow = smem + 27520;                                     // 784 (pre-scaled by log2e)
    float* den  = smem + 28304;                                     // 64

    const int bh = blockIdx.y;
    const int b  = bh >> 3;
    const int h  = bh & 7;
    const int n0 = blockIdx.x * 64;
    const int tid  = threadIdx.x;
    const int lane = tid & 31;
    const int w    = tid >> 5;

    const float* Qb = g_Q + (size_t)bh * KDIM * Nseq;
    const float* Kb = g_K + (size_t)bh * KDIM * Nseq;
    const float* Vb = g_V + (size_t)bh * Nseq * VDIM;

    {
#pragma unroll
        for (int i = 0; i < 2; i++) {
            int g = tid + i * 256;
            int d = g >> 3, c = (g & 7) << 2;
            cpa16(smem_u32(&Kst[0][d][c]), Kb + (size_t)d * Nseq + c);
        }
#pragma unroll
        for (int i = 0; i < 8; i++) {
            int g = tid + i * 256;
            int mm = g >> 6, c = (g & 63) << 2;
            cpa16(smem_u32(&Vs[0][mm][c]), Vb + (size_t)mm * VDIM + c);
        }
        CP_COMMIT();
    }

    for (int i = tid; i < Nseq; i += 256) brow[i] = biases[h * Nseq + i] * LOG2E;

#pragma unroll
    for (int i = 0; i < 4; i++) {
        int s = tid + i * 256;
        int d = s >> 4;
        int q4 = (s & 15) << 2;
        float4 v = (n0 + q4 < Nseq)
                 ? *(const float4*)(Qb + (size_t)d * Nseq + n0 + q4)
                 : make_float4(0.f, 0.f, 0.f, 0.f);
        *(float4*)&Qst[d][q4] = v;
    }

    const int sr = (tid >> 4) << 2;     // S rows (4)
    const int sc = (tid & 15) << 1;     // S keys (2)
    const int ro = w << 3;              // PV rows (8)
    const int co = lane << 2;           // PV cols (4 + 4 at +128)

    int ry[4], rx[4];
#pragma unroll
    for (int i = 0; i < 4; i++) {
        int n = n0 + sr + i;
        int nc = (n < Nseq) ? n : (Nseq - 1);
        ry[i] = nc / RESW;
        rx[i] = nc - ry[i] * RESW;
    }

    unsigned long long o2[4][8];
#pragma unroll
    for (int k = 0; k < 4; k++)
#pragma unroll
        for (int c = 0; c < 8; c++) o2[k][c] = 0ULL;

    float dl[4] = {0.f, 0.f, 0.f, 0.f};   // per-thread den partials
    const float SC2 = SCALEV * LOG2E;

    for (int kt = 0; kt < NKT; kt++) {
        const int buf = kt & 1;
        const int mbase = kt * 32;

        CP_WAIT0();
        __syncthreads();   // tile kt visible; Pt/Kst/Vs reuse safe

        if (kt + 1 < NKT) {
            const int nb = mbase + 32;
#pragma unroll
            for (int i = 0; i < 2; i++) {
                int g = tid + i * 256;
                int d = g >> 3, c = (g & 7) << 2;
                if (nb + c < Nseq)
                    cpa16(smem_u32(&Kst[buf ^ 1][d][c]),
                          Kb + (size_t)d * Nseq + nb + c);
                else
                    *(float4*)&Kst[buf ^ 1][d][c] = make_float4(0.f, 0.f, 0.f, 0.f);
            }
#pragma unroll
            for (int i = 0; i < 8; i++) {
                int g = tid + i * 256;
                int mm = g >> 6, c = (g & 63) << 2;
                if (nb + mm < Nseq)
                    cpa16(smem_u32(&Vs[buf ^ 1][mm][c]),
                          Vb + (size_t)(nb + mm) * VDIM + c);
                else
                    *(float4*)&Vs[buf ^ 1][mm][c] = make_float4(0.f, 0.f, 0.f, 0.f);
            }
        }
        CP_COMMIT();

        // ---- S = Q.K^T: key pair packed as 64-bit FMA2 operand ----
        unsigned long long s2[4] = {0ULL, 0ULL, 0ULL, 0ULL};
#pragma unroll
        for (int d = 0; d < KDIM; d++) {
            float4 qv = *(const float4*)&Qst[d][sr];
            unsigned long long kv = *(const unsigned long long*)&Kst[buf][d][sc];
            unsigned long long qq;
            PACK_FF(qq, qv.x, qv.x); FMA_F32X2(s2[0], qq, kv, s2[0]);
            PACK_FF(qq, qv.y, qv.y); FMA_F32X2(s2[1], qq, kv, s2[1]);
            PACK_FF(qq, qv.z, qv.z); FMA_F32X2(s2[2], qq, kv, s2[2]);
            PACK_FF(qq, qv.w, qv.w); FMA_F32X2(s2[3], qq, kv, s2[3]);
        }
        float s4[4][2];
#pragma unroll
        for (int i = 0; i < 4; i++)
            UNPACK_FF(s4[i][0], s4[i][1], s2[i]);

        int m0 = mbase + sc, m1 = m0 + 1;
        bool v0 = (m0 < Nseq), v1 = (m1 < Nseq);
        int mc0 = v0 ? m0 : (Nseq - 1);
        int mc1 = v1 ? m1 : (Nseq - 1);
        int my0 = mc0 / RESW, mx0 = mc0 - my0 * RESW;
        int my1 = mc1 / RESW, mx1 = mc1 - my1 * RESW;

        // ---- softmax numerators (no max, base-2); per-thread den ----
        float p0v[4], p1v[4];
#pragma unroll
        for (int i = 0; i < 4; i++) {
            float sv0 = v0 ? (s4[i][0] * SC2 + brow[abs(ry[i]-my0) * RESW + abs(rx[i]-mx0)]) : -1e30f;
            float sv1 = v1 ? (s4[i][1] * SC2 + brow[abs(ry[i]-my1) * RESW + abs(rx[i]-mx1)]) : -1e30f;
            p0v[i] = ex2f(sv0);
            p1v[i] = ex2f(sv1);
            dl[i] += p0v[i] + p1v[i];
        }
        *(float4*)&Pt[sc][sr]     = make_float4(p0v[0], p0v[1], p0v[2], p0v[3]);
        *(float4*)&Pt[sc + 1][sr] = make_float4(p1v[0], p1v[1], p1v[2], p1v[3]);
        __syncwarp();   // Pt rows for this warp's PV are warp-local

        // ---- PV: row-pair packed FMA2 over 32 keys ----
#pragma unroll 2
        for (int mm = 0; mm < 32; mm++) {
            ulonglong2 pA = *(const ulonglong2*)&Pt[mm][ro];
            ulonglong2 pB = *(const ulonglong2*)&Pt[mm][ro + 4];
            unsigned long long p2[4] = {pA.x, pA.y, pB.x, pB.y};
            float4 va = *(const float4*)&Vs[buf][mm][co];
            float4 vb = *(const float4*)&Vs[buf][mm][128 + co];
            unsigned long long vd[8];
            PACK_FF(vd[0], va.x, va.x); PACK_FF(vd[1], va.y, va.y);
            PACK_FF(vd[2], va.z, va.z); PACK_FF(vd[3], va.w, va.w);
            PACK_FF(vd[4], vb.x, vb.x); PACK_FF(vd[5], vb.y, vb.y);
            PACK_FF(vd[6], vb.z, vb.z); PACK_FF(vd[7], vb.w, vb.w);
#pragma unroll
            for (int k = 0; k < 4; k++)
#pragma unroll
                for (int c = 0; c < 8; c++)
                    FMA_F32X2(o2[k][c], p2[k], vd[c], o2[k][c]);
        }
    }

    // ---- final den reduction (once): 16-lane group per row block ----
#pragma unroll
    for (int i = 0; i < 4; i++) {
        float ps = dl[i];
#pragma unroll
        for (int off = 8; off; off >>= 1)
            ps += __shfl_xor_sync(0xffffffffu, ps, off);
        if ((tid & 15) == 0) den[sr + i] = ps;
    }
    __syncwarp();   // den rows for this warp's epilogue are warp-local

    // ---- epilogue: normalize, SiLU, RN-round to tf32, store ----
#pragma unroll
    for (int k = 0; k < 4; k++) {
        float lo[8], hi[8];
#pragma unroll
        for (int c = 0; c < 8; c++) UNPACK_FF(lo[c], hi[c], o2[k][c]);
        int r0i = ro + 2 * k;
#pragma unroll
        for (int half = 0; half < 2; half++) {
            int r = r0i + half;
            int n = n0 + r;
            if (n < Nseq) {
                float inv = 1.f / den[r];
                const float* src = half ? hi : lo;
                size_t base = ((size_t)b * Nseq + n) * (Hh * VDIM) + h * VDIM;
                float4 vv0, vv1;
                float t;
                t = src[0] * inv; vv0.x = rn_tf32(t / (1.f + __expf(-t)));
                t = src[1] * inv; vv0.y = rn_tf32(t / (1.f + __expf(-t)));
                t = src[2] * inv; vv0.z = rn_tf32(t / (1.f + __expf(-t)));
                t = src[3] * inv; vv0.w = rn_tf32(t / (1.f + __expf(-t)));
                t = src[4] * inv; vv1.x = rn_tf32(t / (1.f + __expf(-t)));
                t = src[5] * inv; vv1.y = rn_tf32(t / (1.f + __expf(-t)));
                t = src[6] * inv; vv1.z = rn_tf32(t / (1.f + __expf(-t)));
                t = src[7] * inv; vv1.w = rn_tf32(t / (1.f + __expf(-t)));
                *(float4*)(g_AO + base + co)       = vv0;
                *(float4*)(g_AO + base + 128 + co) = vv1;
            }
        }
    }
}

// =====================================================================
// GEMM 2 (TF32 WMMA, cp.async double-buffered, 2 CTAs/SM, 128x128):
// out = BN(AO @ wp^T)   (round-13 verified; 64x128 experiment reverted)
// =====================================================================
__global__ __launch_bounds__(256, 2) void gemm_proj_kernel(
    const float* __restrict__ gamma, const float* __restrict__ beta,
    const float* __restrict__ mean, const float* __restrict__ var,
    float* __restrict__ out)
{
    extern __shared__ float gsm[];
    float (*As)[128][36] = (float(*)[128][36])gsm;
    float (*Bs)[128][36] = (float(*)[128][36])(gsm + 9216);
    float (*stage)[320]  = (float(*)[320])(gsm + 18432);

    const int K  = Hh * VDIM;   // 2048
    const float* A = g_AO;
    const float* W = g_WP;
    const int bm = blockIdx.x * 128;
    const int bn = blockIdx.y * 128;
    const int tid  = threadIdx.x;
    const int wid  = tid >> 5;
    const int lane = tid & 31;
    const int wm = wid & 3;
    const int wn = wid >> 2;

    wmma::fragment<wmma::accumulator, 16, 16, 8, float> cf[2][4];
#pragma unroll
    for (int mi = 0; mi < 2; mi++)
#pragma unroll
        for (int ni = 0; ni < 4; ni++)
            wmma::fill_fragment(cf[mi][ni], 0.f);

#pragma unroll
    for (int i = 0; i < 4; i++) {
        int g = tid + i * 256;
        int row = g >> 3, c4 = (g & 7) << 2;
        cpa16(smem_u32(&As[0][row][c4]), A + (size_t)(bm + row) * K + c4);
        cpa16(smem_u32(&Bs[0][row][c4]), W + (size_t)(bn + row) * K + c4);
    }
    CP_COMMIT();

    for (int k0 = 0; k0 < K; k0 += 32) {
        const int buf = (k0 >> 5) & 1;
        CP_WAIT0();
        __syncthreads();

        if (k0 + 32 < K) {
#pragma unroll
            for (int i = 0; i < 4; i++) {
                int g = tid + i * 256;
                int row = g >> 3, c4 = (g & 7) << 2;
                cpa16(smem_u32(&As[buf ^ 1][row][c4]),
                      A + (size_t)(bm + row) * K + k0 + 32 + c4);
                cpa16(smem_u32(&Bs[buf ^ 1][row][c4]),
                      W + (size_t)(bn + row) * K + k0 + 32 + c4);
            }
        }
        CP_COMMIT();

#pragma unroll
        for (int kk = 0; kk < 32; kk += 8) {
            wmma::fragment<wmma::matrix_b, 16, 16, 8, wmma::precision::tf32, wmma::col_major> bf[4];
#pragma unroll
            for (int ni = 0; ni < 4; ni++)
                wmma::load_matrix_sync(bf[ni], &Bs[buf][wn * 64 + ni * 16][kk], 36);
#pragma unroll
            for (int mi = 0; mi < 2; mi++) {
                wmma::fragment<wmma::matrix_a, 16, 16, 8, wmma::precision::tf32, wmma::row_major> af;
                wmma::load_matrix_sync(af, &As[buf][wm * 32 + mi * 16][kk], 36);
#pragma unroll
                for (int ni = 0; ni < 4; ni++)
                    wmma::mma_sync(cf[mi][ni], af, bf[ni], cf[mi][ni]);
            }
        }
    }

    float* st = &stage[wid][0];
    const int r0 = lane >> 3;
    const int c0 = (lane & 7) << 1;
#pragma unroll
    for (int mi = 0; mi < 2; mi++)
#pragma unroll
        for (int ni = 0; ni < 4; ni++) {
            wmma::store_matrix_sync(st, cf[mi][ni], 20, wmma::mem_row_major);
            __syncwarp();
#pragma unroll
            for (int rr = 0; rr < 4; rr++) {
                int r = r0 + rr * 4;
                int row = bm + wm * 32 + mi * 16 + r;
#pragma unroll
                for (int cc = 0; cc < 2; cc++) {
                    int c = c0 + cc;
                    int col = bn + wn * 64 + ni * 16 + c;
                    float sc = gamma[col] * rsqrtf(var[col] + EPSV);
                    float sh = beta[col] - mean[col] * sc;
                    out[(size_t)row * DIM + col] = st[r * 20 + c] * sc + sh;
                }
            }
            __syncwarp();
        }
}

// =====================================================================
extern "C" void kernel_launch(void* const* d_in, const int* in_sizes, int n_in,
                              void* d_out, int out_size)
{
    const float* x          = (const float*)d_in[0];
    const float* qkv_w      = (const float*)d_in[1];
    const float* qkv_gamma  = (const float*)d_in[2];
    const float* qkv_beta   = (const float*)d_in[3];
    const float* qkv_mean   = (const float*)d_in[4];
    const float* qkv_var    = (const float*)d_in[5];
    const float* att_bias   = (const float*)d_in[6];
    const float* proj_w     = (const float*)d_in[7];
    const float* proj_gamma = (const float*)d_in[8];
    const float* proj_beta  = (const float*)d_in[9];
    const float* proj_mean  = (const float*)d_in[10];
    const float* proj_var   = (const float*)d_in[11];
    // d_in[12] = bias_idxs: computed analytically in-kernel

    cudaFuncSetAttribute(gemm_qkv_kernel,
                         cudaFuncAttributeMaxDynamicSharedMemorySize, GEMM_SMEM);
    cudaFuncSetAttribute(gemm_proj_kernel,
                         cudaFuncAttributeMaxDynamicSharedMemorySize, GEMM_SMEM);
    cudaFuncSetAttribute(attn_kernel,
                         cudaFuncAttributeMaxDynamicSharedMemorySize, ATT_SMEM);

    round_tf32_kernel<<<592, 256>>>(x, qkv_w, proj_w);

    gemm_qkv_kernel<<<dim3(Mrows / 128, QKVO / 128), 256, GEMM_SMEM>>>(
        qkv_gamma, qkv_beta, qkv_mean, qkv_var);

    attn_kernel<<<dim3((Nseq + 63) / 64, Bsz * Hh), 256, ATT_SMEM>>>(att_bias);

    gemm_proj_kernel<<<dim3(Mrows / 128, DIM / 128), 256, GEMM_SMEM>>>(
        proj_gamma, proj_beta, proj_mean, proj_var, (float*)d_out);
}